// round 11
// baseline (speedup 1.0000x reference)
#include <cuda_runtime.h>
#include <cstddef>

#define NN 100000
#define NE 1600000
#define DIM 64
#define N_LAYERS 6
#define UNIT 16              // nodes per transform work unit (per warp)
#define NUNITS (NN / UNIT)   // 6250
#define GUNIT 4              // nodes per gather work unit (per warp)
#define NGUNITS (NN / GUNIT) // 25000

// ---------------- scratch (no allocations allowed) ----------------
__device__ float g_h1[NN * DIM];
__device__ float g_h2[NN * DIM];
__device__ float g_agg[NN * DIM];
__device__ int   g_deg[NN];
__device__ int   g_off[NN + 1];
__device__ int   g_cur[NN];
__device__ int   g_csrc[NE];
__device__ int   g_tk[16];       // [0..5] gather tickets, [8..13] transform tickets

typedef unsigned long long u64;

__device__ __forceinline__ u64 pk2(float x, float y) {
    u64 r; asm("mov.b64 %0,{%1,%2};" : "=l"(r) : "f"(x), "f"(y)); return r;
}
__device__ __forceinline__ void upk2(u64 v, float& x, float& y) {
    asm("mov.b64 {%0,%1},%2;" : "=f"(x), "=f"(y) : "l"(v));
}
__device__ __forceinline__ u64 f2fma(u64 a, u64 b, u64 c) {
    u64 d; asm("fma.rn.f32x2 %0,%1,%2,%3;" : "=l"(d) : "l"(a), "l"(b), "l"(c)); return d;
}
__device__ __forceinline__ u64 relu2(u64 v) {
    float x, y; upk2(v, x, y);
    return pk2(fmaxf(x, 0.f), fmaxf(y, 0.f));
}
__device__ __forceinline__ float4 max4(float4 a, float4 b) {
    return make_float4(fmaxf(a.x, b.x), fmaxf(a.y, b.y),
                       fmaxf(a.z, b.z), fmaxf(a.w, b.w));
}

// ---------------- CSR build ----------------
__global__ void k_count(const int* __restrict__ ei) {
    int e = blockIdx.x * blockDim.x + threadIdx.x;
    if (e < NE) {
        int dst = ei[NE + e];
        if ((unsigned)dst < (unsigned)NN) atomicAdd(&g_deg[dst], 1);
    }
}

__global__ void k_scan() {
    __shared__ int sums[1024];
    int t = threadIdx.x;
    const int C = (NN + 1023) / 1024;
    int start = t * C;
    int end = start + C; if (end > NN) end = NN;
    if (start > NN) start = NN;
    int s = 0;
    for (int i = start; i < end; i++) s += g_deg[i];
    sums[t] = s;
    __syncthreads();
    for (int off = 1; off < 1024; off <<= 1) {
        int v = (t >= off) ? sums[t - off] : 0;
        __syncthreads();
        sums[t] += v;
        __syncthreads();
    }
    int base = (t == 0) ? 0 : sums[t - 1];
    for (int i = start; i < end; i++) {
        int d = g_deg[i];
        g_off[i] = base;
        g_cur[i] = base;
        base += d;
    }
    if (t == 1023) g_off[NN] = base;
    if (t < 16) g_tk[t] = 0;         // reset all tickets every replay
}

__global__ void k_fill(const int* __restrict__ ei) {
    int e = blockIdx.x * blockDim.x + threadIdx.x;
    if (e < NE) {
        int src = ei[e];
        int dst = ei[NE + e];
        if ((unsigned)dst < (unsigned)NN && (unsigned)src < (unsigned)NN) {
            int p = atomicAdd(&g_cur[dst], 1);
            g_csrc[p] = src;
        }
    }
}

// ---------------- gather kernel (no smem -> high occupancy) ----------------
// Warp pulls 4-node tickets. Dual-stream: two nodes' edge loops interleaved,
// half-warp per edge (float4 lanes), 8 LDG.128 (16 edges) in flight.
// Writes agg rows to g_agg.
__global__ __launch_bounds__(256) void k_gather(
    const float* __restrict__ hin_ext, int sel_in, int layer)
{
    const float* hin = (sel_in == 0) ? hin_ext : (sel_in == 1 ? g_h1 : g_h2);
    int lane = threadIdx.x & 31;
    int half = lane >> 4, c4 = (lane & 15) * 4;

    while (true) {
        int u;
        if (lane == 0) u = atomicAdd(&g_tk[layer], 1);
        u = __shfl_sync(0xffffffffu, u, 0);
        if (u >= NGUNITS) break;
        int nb = u * GUNIT;

        #pragma unroll 1
        for (int ln = 0; ln < GUNIT; ln += 2) {
            int i0 = g_off[nb + ln],     e0 = g_off[nb + ln + 1];
            int i1 = g_off[nb + ln + 1], e1 = g_off[nb + ln + 2];
            bool emp0 = (i0 == e0), emp1 = (i1 == e1);
            float4 m0 = make_float4(-3.4e38f, -3.4e38f, -3.4e38f, -3.4e38f);
            float4 m1 = m0;

            while (i0 + 8 <= e0 && i1 + 8 <= e1) {
                int a0 = g_csrc[i0     + half], a1 = g_csrc[i0 + 2 + half];
                int a2 = g_csrc[i0 + 4 + half], a3 = g_csrc[i0 + 6 + half];
                int b0 = g_csrc[i1     + half], b1 = g_csrc[i1 + 2 + half];
                int b2 = g_csrc[i1 + 4 + half], b3 = g_csrc[i1 + 6 + half];
                float4 va0 = *(const float4*)(hin + (size_t)a0 * DIM + c4);
                float4 va1 = *(const float4*)(hin + (size_t)a1 * DIM + c4);
                float4 va2 = *(const float4*)(hin + (size_t)a2 * DIM + c4);
                float4 va3 = *(const float4*)(hin + (size_t)a3 * DIM + c4);
                float4 vb0 = *(const float4*)(hin + (size_t)b0 * DIM + c4);
                float4 vb1 = *(const float4*)(hin + (size_t)b1 * DIM + c4);
                float4 vb2 = *(const float4*)(hin + (size_t)b2 * DIM + c4);
                float4 vb3 = *(const float4*)(hin + (size_t)b3 * DIM + c4);
                m0 = max4(m0, max4(max4(va0, va1), max4(va2, va3)));
                m1 = max4(m1, max4(max4(vb0, vb1), max4(vb2, vb3)));
                i0 += 8; i1 += 8;
            }
            for (; i0 + 8 <= e0; i0 += 8) {
                int a0 = g_csrc[i0     + half], a1 = g_csrc[i0 + 2 + half];
                int a2 = g_csrc[i0 + 4 + half], a3 = g_csrc[i0 + 6 + half];
                float4 v0 = *(const float4*)(hin + (size_t)a0 * DIM + c4);
                float4 v1 = *(const float4*)(hin + (size_t)a1 * DIM + c4);
                float4 v2 = *(const float4*)(hin + (size_t)a2 * DIM + c4);
                float4 v3 = *(const float4*)(hin + (size_t)a3 * DIM + c4);
                m0 = max4(m0, max4(max4(v0, v1), max4(v2, v3)));
            }
            for (; i0 + 2 <= e0; i0 += 2) {
                int s = g_csrc[i0 + half];
                m0 = max4(m0, *(const float4*)(hin + (size_t)s * DIM + c4));
            }
            if (i0 < e0) {
                int s = g_csrc[i0];
                m0 = max4(m0, *(const float4*)(hin + (size_t)s * DIM + c4));
            }
            for (; i1 + 8 <= e1; i1 += 8) {
                int b0 = g_csrc[i1     + half], b1 = g_csrc[i1 + 2 + half];
                int b2 = g_csrc[i1 + 4 + half], b3 = g_csrc[i1 + 6 + half];
                float4 v0 = *(const float4*)(hin + (size_t)b0 * DIM + c4);
                float4 v1 = *(const float4*)(hin + (size_t)b1 * DIM + c4);
                float4 v2 = *(const float4*)(hin + (size_t)b2 * DIM + c4);
                float4 v3 = *(const float4*)(hin + (size_t)b3 * DIM + c4);
                m1 = max4(m1, max4(max4(v0, v1), max4(v2, v3)));
            }
            for (; i1 + 2 <= e1; i1 += 2) {
                int s = g_csrc[i1 + half];
                m1 = max4(m1, *(const float4*)(hin + (size_t)s * DIM + c4));
            }
            if (i1 < e1) {
                int s = g_csrc[i1];
                m1 = max4(m1, *(const float4*)(hin + (size_t)s * DIM + c4));
            }
            m0.x = fmaxf(m0.x, __shfl_xor_sync(0xffffffffu, m0.x, 16));
            m0.y = fmaxf(m0.y, __shfl_xor_sync(0xffffffffu, m0.y, 16));
            m0.z = fmaxf(m0.z, __shfl_xor_sync(0xffffffffu, m0.z, 16));
            m0.w = fmaxf(m0.w, __shfl_xor_sync(0xffffffffu, m0.w, 16));
            m1.x = fmaxf(m1.x, __shfl_xor_sync(0xffffffffu, m1.x, 16));
            m1.y = fmaxf(m1.y, __shfl_xor_sync(0xffffffffu, m1.y, 16));
            m1.z = fmaxf(m1.z, __shfl_xor_sync(0xffffffffu, m1.z, 16));
            m1.w = fmaxf(m1.w, __shfl_xor_sync(0xffffffffu, m1.w, 16));
            if (emp0) m0 = make_float4(0.f, 0.f, 0.f, 0.f);
            if (emp1) m1 = make_float4(0.f, 0.f, 0.f, 0.f);
            if (half == 0) {
                *(float4*)(g_agg + (size_t)(nb + ln) * DIM + c4)     = m0;
                *(float4*)(g_agg + (size_t)(nb + ln + 1) * DIM + c4) = m1;
            }
        }
    }
}

// ---------------- transform kernel (compute-dense) ----------------
// Warp pulls 16-node tickets. Thread = 4 nodes x 8 cols (16 f32x2 accums).
// k<64: z = agg from g_agg (gmem, L2-hot). k>=64: z = h from hin.
// Weights via LDS.128 from transposed smem wt=[Wl;Wr].
__global__ __launch_bounds__(512) void k_transform(
    const float* __restrict__ hin_ext, float* __restrict__ hout_ext,
    int sel_in, int sel_out, int layer,
    const float* __restrict__ Wl, const float* __restrict__ bl,
    const float* __restrict__ Wr, int do_relu)
{
    __shared__ float wt[128 * 64];
    __shared__ float bias[64];

    const float* hin  = (sel_in  == 0) ? hin_ext  : (sel_in  == 1 ? g_h1 : g_h2);
    float*       hout = (sel_out == 0) ? hout_ext : (sel_out == 1 ? g_h1 : g_h2);

    int tid = threadIdx.x;
    for (int i = tid; i < 64 * 64; i += 512) {
        int j = i >> 6, k = i & 63;
        wt[k * 64 + j]        = Wl[i];
        wt[(64 + k) * 64 + j] = Wr[i];
    }
    if (tid < 64) bias[tid] = bl[tid];
    __syncthreads();

    int lane = tid & 31;
    int nidx = lane >> 3, jidx = lane & 7;

    u64 pb0 = pk2(bias[jidx * 8 + 0], bias[jidx * 8 + 1]);
    u64 pb1 = pk2(bias[jidx * 8 + 2], bias[jidx * 8 + 3]);
    u64 pb2 = pk2(bias[jidx * 8 + 4], bias[jidx * 8 + 5]);
    u64 pb3 = pk2(bias[jidx * 8 + 6], bias[jidx * 8 + 7]);

    while (true) {
        int u;
        if (lane == 0) u = atomicAdd(&g_tk[8 + layer], 1);
        u = __shfl_sync(0xffffffffu, u, 0);
        if (u >= NUNITS) break;
        int nb = u * UNIT;
        int n0 = nb + 4 * nidx;

        u64 a0[4], a1[4], a2[4], a3[4];
        #pragma unroll
        for (int i = 0; i < 4; i++) { a0[i] = pb0; a1[i] = pb1; a2[i] = pb2; a3[i] = pb3; }

        // half 1: k in [0,64) -> z = agg (gmem)
        #pragma unroll 2
        for (int k4 = 0; k4 < 64; k4 += 4) {
            float4 zv[4];
            #pragma unroll
            for (int i = 0; i < 4; i++)
                zv[i] = *(const float4*)(g_agg + (size_t)(n0 + i) * DIM + k4);
            #pragma unroll
            for (int kk = 0; kk < 4; kk++) {
                int k = k4 + kk;
                ulonglong2 wa = *(const ulonglong2*)&wt[k * 64 + jidx * 8];
                ulonglong2 wb = *(const ulonglong2*)&wt[k * 64 + jidx * 8 + 4];
                #pragma unroll
                for (int i = 0; i < 4; i++) {
                    float f = (kk == 0) ? zv[i].x : (kk == 1) ? zv[i].y
                            : (kk == 2) ? zv[i].z : zv[i].w;
                    u64 p = pk2(f, f);
                    a0[i] = f2fma(p, wa.x, a0[i]);
                    a1[i] = f2fma(p, wa.y, a1[i]);
                    a2[i] = f2fma(p, wb.x, a2[i]);
                    a3[i] = f2fma(p, wb.y, a3[i]);
                }
            }
        }
        // half 2: k in [64,128) -> z = h (gmem)
        #pragma unroll 2
        for (int k4 = 0; k4 < 64; k4 += 4) {
            float4 zv[4];
            #pragma unroll
            for (int i = 0; i < 4; i++)
                zv[i] = *(const float4*)(hin + (size_t)(n0 + i) * DIM + k4);
            #pragma unroll
            for (int kk = 0; kk < 4; kk++) {
                int k = 64 + k4 + kk;
                ulonglong2 wa = *(const ulonglong2*)&wt[k * 64 + jidx * 8];
                ulonglong2 wb = *(const ulonglong2*)&wt[k * 64 + jidx * 8 + 4];
                #pragma unroll
                for (int i = 0; i < 4; i++) {
                    float f = (kk == 0) ? zv[i].x : (kk == 1) ? zv[i].y
                            : (kk == 2) ? zv[i].z : zv[i].w;
                    u64 p = pk2(f, f);
                    a0[i] = f2fma(p, wa.x, a0[i]);
                    a1[i] = f2fma(p, wa.y, a1[i]);
                    a2[i] = f2fma(p, wb.x, a2[i]);
                    a3[i] = f2fma(p, wb.y, a3[i]);
                }
            }
        }
        #pragma unroll
        for (int i = 0; i < 4; i++) {
            u64 v0 = a0[i], v1 = a1[i], v2 = a2[i], v3 = a3[i];
            if (do_relu) { v0 = relu2(v0); v1 = relu2(v1); v2 = relu2(v2); v3 = relu2(v3); }
            int node = n0 + i;
            ulonglong2 s0, s1;
            s0.x = v0; s0.y = v1; s1.x = v2; s1.y = v3;
            *(ulonglong2*)(hout + (size_t)node * DIM + jidx * 8)     = s0;
            *(ulonglong2*)(hout + (size_t)node * DIM + jidx * 8 + 4) = s1;
        }
    }
}

// ---------------- launch ----------------
extern "C" void kernel_launch(void* const* d_in, const int* in_sizes, int n_in,
                              void* d_out, int out_size)
{
    const float* x  = (const float*)d_in[0];
    const int*   ei = (const int*)d_in[1];
    const float* Wl = (const float*)d_in[2];
    const float* bl = (const float*)d_in[3];
    const float* Wr = (const float*)d_in[4];
    float*       out = (float*)d_out;

    void* deg_ptr = nullptr;
    cudaGetSymbolAddress(&deg_ptr, g_deg);
    cudaMemsetAsync(deg_ptr, 0, NN * sizeof(int));

    k_count<<<(NE + 255) / 256, 256>>>(ei);
    k_scan<<<1, 1024>>>();
    k_fill<<<(NE + 255) / 256, 256>>>(ei);

    const int GGRID = 148 * 6;   // gather: 256-thr blocks, high occupancy
    const int TGRID = 148 * 2;   // transform: 512-thr blocks
    // ping-pong: ext(x) -> g_h1 -> g_h2 -> g_h1 -> g_h2 -> g_h1 -> ext(out)
    int sel_in = 0, sel_out = 1;
    for (int l = 0; l < N_LAYERS; l++) {
        int so = (l == N_LAYERS - 1) ? 0 : sel_out;
        k_gather<<<GGRID, 256>>>(x, sel_in, l);
        k_transform<<<TGRID, 512>>>(x, out, sel_in, so, l,
                                    Wl + (size_t)l * DIM * DIM,
                                    bl + (size_t)l * DIM,
                                    Wr + (size_t)l * DIM * DIM,
                                    (l < N_LAYERS - 1) ? 1 : 0);
        if (l < N_LAYERS - 1) {
            sel_in = sel_out;
            sel_out = (sel_out == 1) ? 2 : 1;
        }
    }
}